// round 3
// baseline (speedup 1.0000x reference)
#include <cuda_runtime.h>

// preds:   (8, 6, 4, 512, 512) fp32  -> 201,326,592 floats
// targets: (8, 6,    512, 512) ints  -> 12,582,912 values (int32 OR int64, detected at runtime)
// out = (1/8) * sum_{n,s,h,w} ( logsumexp_c preds[n,s,:,h,w] - preds[n,s,t,h,w] )

#define HW        262144            // 512*512 = 2^18
#define CHW       (4 * HW)          // 2^20
#define TOTAL_PX  12582912          // 48 * HW
#define THREADS   256
#define NBLOCKS   (TOTAL_PX / THREADS)   // 49152 exactly

static __device__ double g_acc;
static __device__ int    g_stride;   // int32 words per target element: 1 (int32) or 2 (int64 LE)

// Probe: int64 little-endian values in [0,4) have zero in every odd 32-bit word.
// Reads only the first 64 words (256 bytes) — in-bounds under either dtype.
__global__ void nims_ce_probe_kernel(const int* __restrict__ tgt) {
    int all_zero_odd = 1;
    #pragma unroll
    for (int i = 1; i < 64; i += 2)
        if (tgt[i] != 0) { all_zero_odd = 0; }
    g_stride = all_zero_odd ? 2 : 1;
    g_acc = 0.0;
}

__global__ void __launch_bounds__(THREADS)
nims_ce_main_kernel(const float* __restrict__ preds,
                    const int* __restrict__ tgt) {
    int p  = blockIdx.x * THREADS + threadIdx.x;     // pixel id, < TOTAL_PX
    int ns = p >> 18;                                // p / HW
    int hw = p & (HW - 1);                           // p % HW

    const float* base = preds + (long long)ns * CHW + hw;

    // Scalar, perfectly coalesced loads from the 4 channel planes.
    float a = __ldg(base);
    float b = __ldg(base + HW);
    float c = __ldg(base + 2 * HW);
    float d = __ldg(base + 3 * HW);

    int t = __ldg(tgt + (long long)p * g_stride);    // low word is the value for int64 LE

    float m  = fmaxf(fmaxf(a, b), fmaxf(c, d));
    float s  = __expf(a - m) + __expf(b - m) + __expf(c - m) + __expf(d - m);
    float xt = (t == 0) ? a : (t == 1) ? b : (t == 2) ? c : d;
    float local = m + __logf(s) - xt;

    // Warp reduction
    #pragma unroll
    for (int off = 16; off > 0; off >>= 1)
        local += __shfl_xor_sync(0xFFFFFFFF, local, off);

    __shared__ float warp_sums[THREADS / 32];
    int lane = threadIdx.x & 31;
    int wid  = threadIdx.x >> 5;
    if (lane == 0) warp_sums[wid] = local;
    __syncthreads();

    if (wid == 0) {
        float v = (lane < THREADS / 32) ? warp_sums[lane] : 0.0f;
        #pragma unroll
        for (int off = 4; off > 0; off >>= 1)
            v += __shfl_xor_sync(0xFFFFFFFF, v, off);
        if (lane == 0)
            atomicAdd(&g_acc, (double)v);
    }
}

__global__ void nims_ce_finalize_kernel(float* __restrict__ out) {
    out[0] = (float)(g_acc * (1.0 / 8.0));   // mean over N=8
}

extern "C" void kernel_launch(void* const* d_in, const int* in_sizes, int n_in,
                              void* d_out, int out_size) {
    // Role selection by size: preds is strictly the larger buffer under any
    // unit convention (elements or bytes). No equality tests.
    int preds_idx = 0, tgt_idx = 1;
    if (n_in >= 2) {
        long long s0 = in_sizes[0], s1 = in_sizes[1];
        if (s1 > s0) { preds_idx = 1; tgt_idx = 0; }
    }

    const float* preds = (const float*)d_in[preds_idx];
    const int*   tgt   = (const int*)d_in[tgt_idx];
    float*       out   = (float*)d_out;

    nims_ce_probe_kernel<<<1, 1>>>(tgt);
    nims_ce_main_kernel<<<NBLOCKS, THREADS>>>(preds, tgt);
    nims_ce_finalize_kernel<<<1, 1>>>(out);
}

// round 4
// speedup vs baseline: 2.0370x; 2.0370x over previous
#include <cuda_runtime.h>

// preds:   (8, 6, 4, 512, 512) fp32  -> 201,326,592 floats
// targets: (8, 6,    512, 512) ints  -> 12,582,912 values (int32 or int64-LE, detected per block)
// out = (1/8) * sum_{n,s,h,w} ( logsumexp_c preds[n,s,:,h,w] - preds[n,s,t,h,w] )

#define HW        262144                 // 512*512 = 2^18
#define CHW       (4 * HW)               // 2^20
#define TOTAL_PX  12582912               // 48 * HW
#define THREADS   256
#define PXT       4                      // pixels per thread
#define NBLOCKS   (TOTAL_PX / (THREADS * PXT))   // 12288 exactly

static __device__ double g_acc = 0.0;    // reset by finalize each iteration -> graph-deterministic

__device__ __forceinline__ float ce_pixel(float a, float b, float c, float d, int t) {
    float m  = fmaxf(fmaxf(a, b), fmaxf(c, d));
    float s  = __expf(a - m) + __expf(b - m) + __expf(c - m) + __expf(d - m);
    float xt = (t == 0) ? a : (t == 1) ? b : (t == 2) ? c : d;
    return m + __logf(s) - xt;
}

__global__ void __launch_bounds__(THREADS)
nims_ce_main_kernel(const float* __restrict__ preds,
                    const int* __restrict__ tgt) {
    __shared__ int   s_stride2;                 // 1 if targets are int64 (LE), else 0
    __shared__ float warp_sums[THREADS / 32];

    int lane = threadIdx.x & 31;
    int wid  = threadIdx.x >> 5;

    // Per-block dtype probe: int64-LE values in [0,4) => every odd 32-bit word is 0.
    // First 64 words live in L2 after block 0; one coalesced load + ballot.
    if (wid == 0) {
        int w = tgt[2 * lane + 1];
        unsigned nz = __ballot_sync(0xFFFFFFFF, w != 0);
        if (lane == 0) s_stride2 = (nz == 0u);
    }
    __syncthreads();
    int stride2 = s_stride2;

    int p0 = (blockIdx.x * THREADS + threadIdx.x) * PXT;   // < TOTAL_PX, multiple of 4
    int ns = p0 >> 18;
    int hw = p0 & (HW - 1);
    const float* base = preds + (long long)ns * CHW + hw;

    // 4 channel planes x 4 consecutive pixels: coalesced 16B loads.
    float4 v0 = *reinterpret_cast<const float4*>(base);
    float4 v1 = *reinterpret_cast<const float4*>(base + HW);
    float4 v2 = *reinterpret_cast<const float4*>(base + 2 * HW);
    float4 v3 = *reinterpret_cast<const float4*>(base + 3 * HW);

    int t0, t1, t2, t3;
    if (!stride2) {
        int4 t = *reinterpret_cast<const int4*>(tgt + p0);           // 16B aligned
        t0 = t.x; t1 = t.y; t2 = t.z; t3 = t.w;
    } else {
        const int4* tp = reinterpret_cast<const int4*>(tgt + 2LL * p0);  // 32B aligned
        int4 ta = tp[0], tb = tp[1];
        t0 = ta.x; t1 = ta.z; t2 = tb.x; t3 = tb.z;                  // low words of int64-LE
    }

    float local = ce_pixel(v0.x, v1.x, v2.x, v3.x, t0)
                + ce_pixel(v0.y, v1.y, v2.y, v3.y, t1)
                + ce_pixel(v0.z, v1.z, v2.z, v3.z, t2)
                + ce_pixel(v0.w, v1.w, v2.w, v3.w, t3);

    #pragma unroll
    for (int off = 16; off > 0; off >>= 1)
        local += __shfl_xor_sync(0xFFFFFFFF, local, off);

    if (lane == 0) warp_sums[wid] = local;
    __syncthreads();

    if (wid == 0) {
        float v = (lane < THREADS / 32) ? warp_sums[lane] : 0.0f;
        #pragma unroll
        for (int off = 4; off > 0; off >>= 1)
            v += __shfl_xor_sync(0xFFFFFFFF, v, off);
        if (lane == 0)
            atomicAdd(&g_acc, (double)v);
    }
}

__global__ void nims_ce_finalize_kernel(float* __restrict__ out) {
    out[0] = (float)(g_acc * (1.0 / 8.0));   // mean over N=8
    g_acc = 0.0;                              // reset for the next graph replay
}

extern "C" void kernel_launch(void* const* d_in, const int* in_sizes, int n_in,
                              void* d_out, int out_size) {
    // Role selection by size: preds is strictly the larger buffer under any
    // unit convention (elements or bytes).
    int preds_idx = 0, tgt_idx = 1;
    if (n_in >= 2 && (long long)in_sizes[1] > (long long)in_sizes[0]) {
        preds_idx = 1; tgt_idx = 0;
    }

    const float* preds = (const float*)d_in[preds_idx];
    const int*   tgt   = (const int*)d_in[tgt_idx];
    float*       out   = (float*)d_out;

    nims_ce_main_kernel<<<NBLOCKS, THREADS>>>(preds, tgt);
    nims_ce_finalize_kernel<<<1, 1>>>(out);
}